// round 8
// baseline (speedup 1.0000x reference)
#include <cuda_runtime.h>
#include <cuda_bf16.h>
#include <cstdint>

#define N_ENT  40000
#define NPAD   40064      // 313 * 128
#define D      128
#define BATCH  1024
#define NC     2048       // c rows: 2 branches x 1024
#define MTILES 313
#define NTILES 16
#define NTILE_TOT (MTILES * NTILES)   // 5008
#define GRID_MAIN 296

// ---------------- device scratch (static globals: allocation-free) ----------
static __device__ double g_acc;
static __device__ unsigned int g_tile;   // work-queue cursor
static __device__ unsigned int g_done;   // finished-CTA counter
static __device__ __align__(16) __nv_bfloat16 g_ebf[NPAD * D];  // ent bf16 row-major
static __device__ __align__(16) __nv_bfloat16 g_cbf[NC * D];    // c   bf16 row-major
static __device__ __align__(16) float g_ne4[NPAD];  // |ent_j|^2 * 1e-4
static __device__ __align__(16) float g_nb4[NC];    // |c_i|^2   * 1e-4
static __device__ __align__(16) int   g_ti[NC];     // pos_t (branch0) / -1 (branch1)

// ---------------- helpers ---------------------------------------------------
static __device__ __forceinline__ uint32_t smem_u32(const void* p) {
    uint32_t a;
    asm("{ .reg .u64 t; cvta.to.shared.u64 t, %1; cvt.u32.u64 %0, t; }" : "=r"(a) : "l"(p));
    return a;
}

static __device__ __forceinline__ void cp_async16(uint32_t sdst, const void* gsrc) {
    asm volatile("cp.async.cg.shared.global [%0], [%1], 16;" :: "r"(sdst), "l"(gsrc) : "memory");
}
#define CP_COMMIT() asm volatile("cp.async.commit_group;" ::: "memory")
#define CP_WAIT0()  asm volatile("cp.async.wait_group 0;" ::: "memory")

#define LDSM_X4(r0, r1, r2, r3, addr) \
    asm volatile("ldmatrix.sync.aligned.m8n8.x4.shared.b16 {%0,%1,%2,%3}, [%4];" \
        : "=r"(r0), "=r"(r1), "=r"(r2), "=r"(r3) : "r"(addr))
#define LDSM_X4_T(r0, r1, r2, r3, addr) \
    asm volatile("ldmatrix.sync.aligned.m8n8.x4.trans.shared.b16 {%0,%1,%2,%3}, [%4];" \
        : "=r"(r0), "=r"(r1), "=r"(r2), "=r"(r3) : "r"(addr))

static __device__ __forceinline__ void mma16816(float* c, const uint32_t* a,
                                                uint32_t b0, uint32_t b1) {
    asm volatile("mma.sync.aligned.m16n8k16.row.col.f32.bf16.bf16.f32 "
        "{%0,%1,%2,%3}, {%4,%5,%6,%7}, {%8,%9}, {%0,%1,%2,%3};"
        : "+f"(c[0]), "+f"(c[1]), "+f"(c[2]), "+f"(c[3])
        : "r"(a[0]), "r"(a[1]), "r"(a[2]), "r"(a[3]), "r"(b0), "r"(b1));
}

// ---------------------------------------------------------------------------
// Prep: 2 rows per warp (MLP=2). ent -> row-major bf16 (+zero pad rows),
// c rows (ent[h]+rseq) -> bf16, pre-scaled fp32 norms, target indices.
// Also resets the work-queue + accumulators (graph replays!).
// ---------------------------------------------------------------------------
__global__ __launch_bounds__(256) void prep_kernel(
        const float* __restrict__ ent,
        const int* __restrict__ pos_h, const int* __restrict__ pos_t,
        const int* __restrict__ neg_h,
        const float* __restrict__ rpos, const float* __restrict__ rneg) {
    const int lane  = threadIdx.x & 31;
    const int warp  = blockIdx.x * 8 + (threadIdx.x >> 5);
    if (blockIdx.x == 0 && threadIdx.x == 0) {
        g_acc = 0.0; g_tile = GRID_MAIN; g_done = 0;
    }
    const float4* ent4 = reinterpret_cast<const float4*>(ent);

    #pragma unroll
    for (int rr = 0; rr < 2; ++rr) {
        const int row = warp * 2 + rr;
        if (row < NPAD) {
            float4 v = make_float4(0.f, 0.f, 0.f, 0.f);
            if (row < N_ENT) v = ent4[(size_t)row * 32 + lane];
            float s = v.x * v.x + v.y * v.y + v.z * v.z + v.w * v.w;
            #pragma unroll
            for (int o = 16; o > 0; o >>= 1) s += __shfl_xor_sync(0xffffffffu, s, o);
            if (lane == 0) g_ne4[row] = s * 1e-4f;
            __nv_bfloat162 p0 = __float22bfloat162_rn(make_float2(v.x, v.y));
            __nv_bfloat162 p1 = __float22bfloat162_rn(make_float2(v.z, v.w));
            uint2 p; p.x = *reinterpret_cast<uint32_t*>(&p0); p.y = *reinterpret_cast<uint32_t*>(&p1);
            reinterpret_cast<uint2*>(g_ebf)[(size_t)row * 32 + lane] = p;
        } else if (row < NPAD + NC) {
            int i  = row - NPAD;
            int br = i >> 10, bi = i & 1023;
            int h  = br ? neg_h[bi] : pos_h[bi];
            float4 e = ent4[(size_t)h * 32 + lane];
            const float4* rrp = reinterpret_cast<const float4*>(br ? rneg : rpos);
            float4 q = rrp[(size_t)bi * 32 + lane];
            float4 c = make_float4(e.x + q.x, e.y + q.y, e.z + q.z, e.w + q.w);
            float s = c.x * c.x + c.y * c.y + c.z * c.z + c.w * c.w;
            #pragma unroll
            for (int o = 16; o > 0; o >>= 1) s += __shfl_xor_sync(0xffffffffu, s, o);
            if (lane == 0) { g_nb4[i] = s * 1e-4f; g_ti[i] = br ? -1 : pos_t[bi]; }
            __nv_bfloat162 p0 = __float22bfloat162_rn(make_float2(c.x, c.y));
            __nv_bfloat162 p1 = __float22bfloat162_rn(make_float2(c.z, c.w));
            uint2 p; p.x = *reinterpret_cast<uint32_t*>(&p0); p.y = *reinterpret_cast<uint32_t*>(&p1);
            reinterpret_cast<uint2*>(g_cbf)[(size_t)i * 32 + lane] = p;
        }
    }
}

// ---------------------------------------------------------------------------
// Persistent main kernel: atomic tile queue over 5008 (mT,nT) tiles, n-major.
// Per tile: 128x128x128 HMMA (8 warps, 32x64 warp tiles), fused loss epilogue.
// Next tile's cp.async is issued in-place right after the mainloop (tile smem
// is dead then), overlapping the load with the MUFU-heavy epilogue.
// Small per-tile arrays (ne4/na4/ti) are 2-deep double buffered.
// ---------------------------------------------------------------------------
#define SM_A     0
#define SM_B     32768
#define SM_NE    65536     // 2 x 128 f
#define SM_NA    66560     // 2 x 128 f
#define SM_TI    67584     // 2 x 128 i
#define SM_RED   68608     // 8 f
#define SM_CTR   68640     // 1 u32
#define SM_BYTES 68672

static __device__ __forceinline__ void prefetch_tile(uint32_t sb, int tid, int buf,
                                                     int mG, int nG) {
    // big tiles: 8 iters x 256 threads x 16B each, swizzled
    #pragma unroll
    for (int it = 0; it < 8; ++it) {
        int idx = it * 256 + tid;
        int row = idx >> 4, cc = idx & 15;
        uint32_t sw = (uint32_t)((cc ^ (row & 7)) << 4);
        cp_async16(sb + SM_A + row * 256 + sw, g_ebf + (size_t)(mG + row) * D + cc * 8);
        cp_async16(sb + SM_B + row * 256 + sw, g_cbf + (size_t)(nG + row) * D + cc * 8);
    }
    // small arrays (512B each): threads 0-31 ne, 32-63 na, 64-95 ti
    if (tid < 32) {
        cp_async16(sb + SM_NE + buf * 512 + tid * 16, g_ne4 + mG + tid * 4);
    } else if (tid < 64) {
        int l = tid - 32;
        cp_async16(sb + SM_NA + buf * 512 + l * 16, g_nb4 + nG + l * 4);
    } else if (tid < 96) {
        int l = tid - 64;
        cp_async16(sb + SM_TI + buf * 512 + l * 16, g_ti + nG + l * 4);
    }
    CP_COMMIT();
}

__global__ __launch_bounds__(256, 2) void loss_main_kernel(float* __restrict__ out) {
    extern __shared__ __align__(16) uint8_t smem[];
    const uint32_t sb = smem_u32(smem);
    float* s_red = reinterpret_cast<float*>(smem + SM_RED);
    unsigned int* s_ctr = reinterpret_cast<unsigned int*>(smem + SM_CTR);

    const int tid  = threadIdx.x;
    const int wid  = tid >> 5;
    const int lane = tid & 31;
    const int wm   = wid >> 1;            // 0..3  (M sub-tile of 32)
    const int wn   = wid & 1;             // 0..1  (N sub-tile of 64)

    unsigned int tile = blockIdx.x;
    int buf = 0;
    int mT = tile % MTILES, nT = tile / MTILES;
    int mG = mT * 128, nG = nT * 128;
    prefetch_tile(sb, tid, buf, mG, nG);

    for (;;) {
        if (tid == 0) *s_ctr = atomicAdd(&g_tile, 1u);
        CP_WAIT0();
        __syncthreads();                 // tile + small arrays visible; s_ctr visible

        // ---- MMA mainloop: K = 8 steps of 16 ----
        float acc[2][8][4];
        #pragma unroll
        for (int mt = 0; mt < 2; ++mt)
            #pragma unroll
            for (int jn = 0; jn < 8; ++jn)
                #pragma unroll
                for (int e = 0; e < 4; ++e) acc[mt][jn][e] = 0.f;

        #pragma unroll
        for (int ks = 0; ks < 8; ++ks) {
            uint32_t a[2][4], b[4][4];
            #pragma unroll
            for (int mt = 0; mt < 2; ++mt) {
                int row = wm * 32 + mt * 16 + (lane & 15);
                int cc  = 2 * ks + (lane >> 4);
                uint32_t ad = sb + SM_A + row * 256 + (uint32_t)((cc ^ (row & 7)) << 4);
                LDSM_X4(a[mt][0], a[mt][1], a[mt][2], a[mt][3], ad);
            }
            #pragma unroll
            for (int j = 0; j < 4; ++j) {
                int row = wn * 64 + j * 16 + (lane & 7) + ((lane >> 4) << 3);
                int cc  = 2 * ks + ((lane >> 3) & 1);
                uint32_t bd = sb + SM_B + row * 256 + (uint32_t)((cc ^ (row & 7)) << 4);
                LDSM_X4_T(b[j][0], b[j][1], b[j][2], b[j][3], bd);
            }
            #pragma unroll
            for (int mt = 0; mt < 2; ++mt)
                #pragma unroll
                for (int jn = 0; jn < 8; ++jn)
                    mma16816(acc[mt][jn], a[mt], b[jn >> 1][(jn & 1) * 2], b[jn >> 1][(jn & 1) * 2 + 1]);
        }

        unsigned int nxt = *s_ctr;       // safe: written pre-sync by tid0
        __syncthreads();                 // all warps done with smem tiles

        // ---- prefetch next tile in place (hidden under epilogue) ----
        if (nxt < NTILE_TOT) {
            int nmT = nxt % MTILES, nnT = nxt / MTILES;
            prefetch_tile(sb, tid, buf ^ 1, nmT * 128, nnT * 128);
        }

        // ---- fused loss epilogue (reads old small-array buffer) ----
        const float* s_ne4 = reinterpret_cast<const float*>(smem + SM_NE + buf * 512);
        const float* s_na4 = reinterpret_cast<const float*>(smem + SM_NA + buf * 512);
        const int*   s_ti  = reinterpret_cast<const int*>(smem + SM_TI + buf * 512);

        const int r0l = wm * 32 + (lane >> 2);
        const int c0l = wn * 64 + 2 * (lane & 3);
        float local = 0.f;
        #pragma unroll
        for (int mt = 0; mt < 2; ++mt) {
            #pragma unroll
            for (int half = 0; half < 2; ++half) {
                const int ml = r0l + mt * 16 + half * 8;
                const int m  = mG + ml;
                const float ne4  = s_ne4[ml];
                const bool valid = (m < N_ENT);
                #pragma unroll
                for (int jn = 0; jn < 8; ++jn) {
                    const int cl = c0l + jn * 8;
                    #pragma unroll
                    for (int e = 0; e < 2; ++e) {
                        float dot = acc[mt][jn][half * 2 + e];
                        int col   = cl + e;
                        // sq4 = 1e-4 * squared distance; u = 100/dist = rsqrt(sq4)
                        float sq4 = fmaxf(fmaf(dot, -2e-4f, ne4 + s_na4[col]), 1e-28f);
                        float u   = rsqrtf(sq4);
                        float ex  = exp2f(-1.442695041f * u);
                        // log(1-clip(sigmoid)) ~= max(-u - e^-u, log 2^-23)
                        float t = fmaxf(fmaf(ex, -1.f, -u), -15.9423847f);
                        // diagonal: log(clip(sigmoid)) ~= min(-e^-u, log(1-2^-23))
                        if (s_ti[col] == m) t = fminf(-ex, -1.1920930e-7f);
                        if (valid) local += t;
                    }
                }
            }
        }

        #pragma unroll
        for (int o = 16; o > 0; o >>= 1) local += __shfl_xor_sync(0xffffffffu, local, o);
        if (lane == 0) s_red[wid] = local;
        __syncthreads();
        if (tid == 0) {
            float s = 0.f;
            #pragma unroll
            for (int w = 0; w < 8; ++w) s += s_red[w];
            atomicAdd(&g_acc, (double)s);
        }

        if (nxt >= NTILE_TOT) break;
        buf ^= 1;
        mT = nxt % MTILES; nT = nxt / MTILES;
        mG = mT * 128; nG = nT * 128;
        __syncthreads();                 // s_red consumed before reuse
    }

    // ---- last CTA out writes the scalar ----
    if (tid == 0) {
        __threadfence();
        unsigned int d = atomicAdd(&g_done, 1u);
        if (d == GRID_MAIN - 1) {
            double a = *((volatile double*)&g_acc);
            out[0] = (float)(-a / ((double)BATCH * (double)N_ENT));
        }
    }
}

extern "C" void kernel_launch(void* const* d_in, const int* in_sizes, int n_in,
                              void* d_out, int out_size) {
    const int*   pos_h = (const int*)d_in[0];
    const int*   pos_t = (const int*)d_in[1];
    const int*   neg_h = (const int*)d_in[2];
    // d_in[3] = neg_t_batch: unused by the reference math.
    const float* rpos  = (const float*)d_in[4];
    const float* rneg  = (const float*)d_in[5];
    const float* ent   = (const float*)d_in[6];
    // d_in[7] = L1_flag: fixed 0 (Euclidean path).

    cudaFuncSetAttribute(loss_main_kernel,
                         cudaFuncAttributeMaxDynamicSharedMemorySize, SM_BYTES);

    int rows = NPAD + NC;                 // 2 rows per warp, 8 warps per block
    prep_kernel<<<(rows + 15) / 16, 256>>>(ent, pos_h, pos_t, neg_h, rpos, rneg);

    loss_main_kernel<<<GRID_MAIN, 256, SM_BYTES>>>((float*)d_out);
}

// round 10
// speedup vs baseline: 1.1092x; 1.1092x over previous
#include <cuda_runtime.h>
#include <cuda_bf16.h>
#include <cstdint>

#define N_ENT  40000
#define NPAD   40064      // 313 * 128
#define D      128
#define BATCH  1024
#define NC     2048       // c rows: 2 branches x 1024
#define MTILES 313
#define NTILES 16
#define NTILE_TOT (MTILES * NTILES)   // 5008
#define GRID_MAIN 296
#define BETA   0.0141421356f          // sqrt(2e-4)

// ---------------- device scratch (static globals: allocation-free) ----------
static __device__ double g_acc;
static __device__ unsigned int g_tile;
static __device__ unsigned int g_done;
static __device__ __align__(16) __nv_bfloat16 g_ebf[NPAD * D];  // -beta * ent (pad rows 0)
static __device__ __align__(16) __nv_bfloat16 g_cbf[NC * D];    // +beta * c
static __device__ __align__(16) float g_ne4[NPAD];  // |ent_j|^2 * 1e-4 (0 for pads)
static __device__ __align__(16) float g_nb4[NC];    // |c_i|^2   * 1e-4

// ---------------- helpers ---------------------------------------------------
static __device__ __forceinline__ uint32_t smem_u32(const void* p) {
    uint32_t a;
    asm("{ .reg .u64 t; cvta.to.shared.u64 t, %1; cvt.u32.u64 %0, t; }" : "=r"(a) : "l"(p));
    return a;
}

static __device__ __forceinline__ void cp_async16(uint32_t sdst, const void* gsrc) {
    asm volatile("cp.async.cg.shared.global [%0], [%1], 16;" :: "r"(sdst), "l"(gsrc) : "memory");
}
#define CP_COMMIT() asm volatile("cp.async.commit_group;" ::: "memory")
#define CP_WAIT0()  asm volatile("cp.async.wait_group 0;" ::: "memory")

#define LDSM_X4(r0, r1, r2, r3, addr) \
    asm volatile("ldmatrix.sync.aligned.m8n8.x4.shared.b16 {%0,%1,%2,%3}, [%4];" \
        : "=r"(r0), "=r"(r1), "=r"(r2), "=r"(r3) : "r"(addr))
#define LDSM_X4_T(r0, r1, r2, r3, addr) \
    asm volatile("ldmatrix.sync.aligned.m8n8.x4.trans.shared.b16 {%0,%1,%2,%3}, [%4];" \
        : "=r"(r0), "=r"(r1), "=r"(r2), "=r"(r3) : "r"(addr))

static __device__ __forceinline__ void mma16816(float* c, const uint32_t* a,
                                                uint32_t b0, uint32_t b1) {
    asm volatile("mma.sync.aligned.m16n8k16.row.col.f32.bf16.bf16.f32 "
        "{%0,%1,%2,%3}, {%4,%5,%6,%7}, {%8,%9}, {%0,%1,%2,%3};"
        : "+f"(c[0]), "+f"(c[1]), "+f"(c[2]), "+f"(c[3])
        : "r"(a[0]), "r"(a[1]), "r"(a[2]), "r"(a[3]), "r"(b0), "r"(b1));
}

static __device__ __forceinline__ uint32_t pack_bf16(float x, float y) {
    __nv_bfloat162 p = __float22bfloat162_rn(make_float2(x, y));
    return *reinterpret_cast<uint32_t*>(&p);
}

// ---------------------------------------------------------------------------
// Prep (proven round-8 structure, + beta prescale, fp32 norms*1e-4):
// 2 rows per warp. Resets queue/accumulator for graph replays.
// ---------------------------------------------------------------------------
__global__ __launch_bounds__(256) void prep_kernel(
        const float* __restrict__ ent,
        const int* __restrict__ pos_h, const int* __restrict__ neg_h,
        const float* __restrict__ rpos, const float* __restrict__ rneg) {
    const int lane  = threadIdx.x & 31;
    const int warp  = blockIdx.x * 8 + (threadIdx.x >> 5);
    if (blockIdx.x == 0 && threadIdx.x == 0) {
        g_acc = 0.0; g_tile = GRID_MAIN; g_done = 0;
    }
    const float4* ent4 = reinterpret_cast<const float4*>(ent);

    #pragma unroll
    for (int rr = 0; rr < 2; ++rr) {
        const int row = warp * 2 + rr;
        if (row < NPAD) {
            float4 v = make_float4(0.f, 0.f, 0.f, 0.f);
            if (row < N_ENT) v = ent4[(size_t)row * 32 + lane];
            float s = v.x * v.x + v.y * v.y + v.z * v.z + v.w * v.w;
            #pragma unroll
            for (int o = 16; o > 0; o >>= 1) s += __shfl_xor_sync(0xffffffffu, s, o);
            if (lane == 0) g_ne4[row] = s * 1e-4f;
            uint2 p;
            p.x = pack_bf16(-BETA * v.x, -BETA * v.y);
            p.y = pack_bf16(-BETA * v.z, -BETA * v.w);
            reinterpret_cast<uint2*>(g_ebf)[(size_t)row * 32 + lane] = p;
        } else if (row < NPAD + NC) {
            int i  = row - NPAD;
            int br = i >> 10, bi = i & 1023;
            int h  = br ? neg_h[bi] : pos_h[bi];
            float4 e = ent4[(size_t)h * 32 + lane];
            const float4* rrp = reinterpret_cast<const float4*>(br ? rneg : rpos);
            float4 q = rrp[(size_t)bi * 32 + lane];
            float4 c = make_float4(e.x + q.x, e.y + q.y, e.z + q.z, e.w + q.w);
            float s = c.x * c.x + c.y * c.y + c.z * c.z + c.w * c.w;
            #pragma unroll
            for (int o = 16; o > 0; o >>= 1) s += __shfl_xor_sync(0xffffffffu, s, o);
            if (lane == 0) g_nb4[i] = s * 1e-4f;
            uint2 p;
            p.x = pack_bf16(BETA * c.x, BETA * c.y);
            p.y = pack_bf16(BETA * c.z, BETA * c.w);
            reinterpret_cast<uint2*>(g_cbf)[(size_t)i * 32 + lane] = p;
        }
    }
}

// ---------------------------------------------------------------------------
// Diagonal correction: for each positive pair (i, t_i), replace the off-diag
// term the main kernel computes with the true diagonal term. Uses the SAME
// bf16 rows and fp32 norms, so it cancels main's contribution to ~ulp.
// ---------------------------------------------------------------------------
__global__ __launch_bounds__(256) void corr_kernel(const int* __restrict__ pos_t) {
    __shared__ double s_c[8];
    const int wid  = threadIdx.x >> 5;
    const int lane = threadIdx.x & 31;
    const int i    = blockIdx.x * 8 + wid;     // 0..1023
    const int t    = pos_t[i];

    const uint2 ua = reinterpret_cast<const uint2*>(g_ebf + (size_t)t * D)[lane];
    const uint2 ub = reinterpret_cast<const uint2*>(g_cbf + (size_t)i * D)[lane];
    float2 a0 = __bfloat1622float2(*reinterpret_cast<const __nv_bfloat162*>(&ua.x));
    float2 a1 = __bfloat1622float2(*reinterpret_cast<const __nv_bfloat162*>(&ua.y));
    float2 b0 = __bfloat1622float2(*reinterpret_cast<const __nv_bfloat162*>(&ub.x));
    float2 b1 = __bfloat1622float2(*reinterpret_cast<const __nv_bfloat162*>(&ub.y));
    float s = a0.x * b0.x + a0.y * b0.y + a1.x * b1.x + a1.y * b1.y;
    #pragma unroll
    for (int o = 16; o > 0; o >>= 1) s += __shfl_xor_sync(0xffffffffu, s, o);

    if (lane == 0) {
        float sq4 = s + g_ne4[t] + g_nb4[i];          // 1e-4 * dist^2
        float u   = rsqrtf(sq4);                      // = 100/dist
        float ex  = exp2f(-1.442695041f * u);
        float off = -fminf(u + ex, 16.118095651f);    // what main contributed
        float dia = fminf(-ex, -1.00000005e-7f);      // true diagonal log(pred)
        s_c[wid] = (double)(dia - off);
    }
    __syncthreads();
    if (threadIdx.x == 0) {
        double tt = 0.0;
        #pragma unroll
        for (int w = 0; w < 8; ++w) tt += s_c[w];
        atomicAdd(&g_acc, tt);
    }
}

// ---------------------------------------------------------------------------
// Persistent main kernel (proven round-8 MMA path): 128x128x128 HMMA tiles,
// atomic queue, in-place prefetch under the epilogue. Lean epilogue:
// sq4 = acc + ne4 + na4 (prescaled inputs), 8 instrs/elem, no diagonal.
// ---------------------------------------------------------------------------
#define SM_A     0
#define SM_B     32768
#define SM_NE    65536     // 2 x 128 f (double buffered)
#define SM_NA    66560     // 2 x 128 f
#define SM_RED   67584     // 8 f
#define SM_CTR   67616     // 1 u32
#define SM_BYTES 67648

static __device__ __forceinline__ void prefetch_tile(uint32_t sb, int tid, int buf,
                                                     int mG, int nG) {
    #pragma unroll
    for (int it = 0; it < 8; ++it) {
        int idx = it * 256 + tid;
        int row = idx >> 4, cc = idx & 15;
        uint32_t sw = (uint32_t)((cc ^ (row & 7)) << 4);
        cp_async16(sb + SM_A + row * 256 + sw, g_ebf + (size_t)(mG + row) * D + cc * 8);
        cp_async16(sb + SM_B + row * 256 + sw, g_cbf + (size_t)(nG + row) * D + cc * 8);
    }
    if (tid < 32) {
        cp_async16(sb + SM_NE + buf * 512 + tid * 16, g_ne4 + mG + tid * 4);
    } else if (tid < 64) {
        int l = tid - 32;
        cp_async16(sb + SM_NA + buf * 512 + l * 16, g_nb4 + nG + l * 4);
    }
    CP_COMMIT();
}

__global__ __launch_bounds__(256, 2) void loss_main_kernel(float* __restrict__ out) {
    extern __shared__ __align__(16) uint8_t smem[];
    const uint32_t sb = smem_u32(smem);
    float* s_red = reinterpret_cast<float*>(smem + SM_RED);
    unsigned int* s_ctr = reinterpret_cast<unsigned int*>(smem + SM_CTR);

    const int tid  = threadIdx.x;
    const int wid  = tid >> 5;
    const int lane = tid & 31;
    const int wm   = wid >> 1;            // 0..3  (32-row M strip)
    const int wn   = wid & 1;             // 0..1  (64-col N strip)

    unsigned int tile = blockIdx.x;
    int buf = 0;
    int mG = (int)(tile % MTILES) * 128, nG = (int)(tile / MTILES) * 128;
    prefetch_tile(sb, tid, buf, mG, nG);

    for (;;) {
        if (tid == 0) *s_ctr = atomicAdd(&g_tile, 1u);
        CP_WAIT0();
        __syncthreads();

        float acc[2][8][4];
        #pragma unroll
        for (int mt = 0; mt < 2; ++mt)
            #pragma unroll
            for (int jn = 0; jn < 8; ++jn)
                #pragma unroll
                for (int e = 0; e < 4; ++e) acc[mt][jn][e] = 0.f;

        #pragma unroll
        for (int ks = 0; ks < 8; ++ks) {
            uint32_t a[2][4], b[4][4];
            #pragma unroll
            for (int mt = 0; mt < 2; ++mt) {
                int row = wm * 32 + mt * 16 + (lane & 15);
                int cc  = 2 * ks + (lane >> 4);
                uint32_t ad = sb + SM_A + row * 256 + (uint32_t)((cc ^ (row & 7)) << 4);
                LDSM_X4(a[mt][0], a[mt][1], a[mt][2], a[mt][3], ad);
            }
            #pragma unroll
            for (int j = 0; j < 4; ++j) {
                int row = wn * 64 + j * 16 + (lane & 7) + ((lane >> 4) << 3);
                int cc  = 2 * ks + ((lane >> 3) & 1);
                uint32_t bd = sb + SM_B + row * 256 + (uint32_t)((cc ^ (row & 7)) << 4);
                LDSM_X4_T(b[j][0], b[j][1], b[j][2], b[j][3], bd);
            }
            #pragma unroll
            for (int mt = 0; mt < 2; ++mt)
                #pragma unroll
                for (int jn = 0; jn < 8; ++jn)
                    mma16816(acc[mt][jn], a[mt], b[jn >> 1][(jn & 1) * 2], b[jn >> 1][(jn & 1) * 2 + 1]);
        }

        unsigned int nxt = *s_ctr;
        __syncthreads();                  // smem tiles dead

        if (nxt < NTILE_TOT)
            prefetch_tile(sb, tid, buf ^ 1, (int)(nxt % MTILES) * 128,
                                            (int)(nxt / MTILES) * 128);

        // ---- lean epilogue: sq4 = acc + ne4 + na4 == 1e-4 * dist^2 ----
        const float* sne = reinterpret_cast<const float*>(smem + SM_NE + buf * 512);
        const float* sna = reinterpret_cast<const float*>(smem + SM_NA + buf * 512);
        const int r0l = wm * 32 + (lane >> 2);
        const int c0l = wn * 64 + 2 * (lane & 3);

        float ner[4];
        #pragma unroll
        for (int q = 0; q < 4; ++q) ner[q] = sne[r0l + q * 8];   // q = mt*2+half
        float2 nac[8];
        const float2* sna2 = reinterpret_cast<const float2*>(sna);
        #pragma unroll
        for (int jn = 0; jn < 8; ++jn) nac[jn] = sna2[(c0l + jn * 8) >> 1];

        float local = 0.f;
        if (mG + 128 <= N_ENT) {          // fast path: all rows valid (312/313 tiles)
            #pragma unroll
            for (int mt = 0; mt < 2; ++mt) {
                #pragma unroll
                for (int half = 0; half < 2; ++half) {
                    const float ne = ner[mt * 2 + half];
                    #pragma unroll
                    for (int jn = 0; jn < 8; ++jn) {
                        float2 na2 = nac[jn];
                        #pragma unroll
                        for (int e = 0; e < 2; ++e) {
                            float sq4 = acc[mt][jn][half * 2 + e] + ne + (e ? na2.y : na2.x);
                            float u   = rsqrtf(sq4);
                            float ex  = exp2f(-1.442695041f * u);
                            local += fminf(u + ex, 16.118095651f);
                        }
                    }
                }
            }
        } else {                           // boundary tile
            #pragma unroll
            for (int mt = 0; mt < 2; ++mt) {
                #pragma unroll
                for (int half = 0; half < 2; ++half) {
                    const bool valid = (mG + r0l + mt * 16 + half * 8) < N_ENT;
                    const float ne = ner[mt * 2 + half];
                    #pragma unroll
                    for (int jn = 0; jn < 8; ++jn) {
                        float2 na2 = nac[jn];
                        #pragma unroll
                        for (int e = 0; e < 2; ++e) {
                            float sq4 = acc[mt][jn][half * 2 + e] + ne + (e ? na2.y : na2.x);
                            float u   = rsqrtf(sq4);
                            float ex  = exp2f(-1.442695041f * u);
                            float m   = fminf(u + ex, 16.118095651f);
                            if (valid) local += m;
                        }
                    }
                }
            }
        }
        local = -local;

        #pragma unroll
        for (int o = 16; o > 0; o >>= 1) local += __shfl_xor_sync(0xffffffffu, local, o);
        if (lane == 0) s_red[wid] = local;
        __syncthreads();
        if (tid == 0) {
            float s = 0.f;
            #pragma unroll
            for (int w = 0; w < 8; ++w) s += s_red[w];
            atomicAdd(&g_acc, (double)s);
        }

        if (nxt >= NTILE_TOT) break;
        buf ^= 1;
        mG = (int)(nxt % MTILES) * 128; nG = (int)(nxt / MTILES) * 128;
        __syncthreads();
    }

    if (tid == 0) {
        __threadfence();
        unsigned int d = atomicAdd(&g_done, 1u);
        if (d == GRID_MAIN - 1) {
            double a = *((volatile double*)&g_acc);
            out[0] = (float)(-a / ((double)BATCH * (double)N_ENT));
        }
    }
}

extern "C" void kernel_launch(void* const* d_in, const int* in_sizes, int n_in,
                              void* d_out, int out_size) {
    const int*   pos_h = (const int*)d_in[0];
    const int*   pos_t = (const int*)d_in[1];
    const int*   neg_h = (const int*)d_in[2];
    // d_in[3] = neg_t_batch: unused by the reference math.
    const float* rpos  = (const float*)d_in[4];
    const float* rneg  = (const float*)d_in[5];
    const float* ent   = (const float*)d_in[6];
    // d_in[7] = L1_flag: fixed 0 (Euclidean path).

    cudaFuncSetAttribute(loss_main_kernel,
                         cudaFuncAttributeMaxDynamicSharedMemorySize, SM_BYTES);

    int rows = NPAD + NC;                 // 2 rows per warp, 8 warps per block
    prep_kernel<<<(rows + 15) / 16, 256>>>(ent, pos_h, neg_h, rpos, rneg);
    corr_kernel<<<BATCH / 8, 256>>>(pos_t);
    loss_main_kernel<<<GRID_MAIN, 256, SM_BYTES>>>((float*)d_out);
}